// round 1
// baseline (speedup 1.0000x reference)
#include <cuda_runtime.h>
#include <cstdint>
#include <cmath>

#define T_SEQ 256
#define BATCH 64
#define EMB   512
#define HID   1024
#define GATES 4096   // 4*HID, PyTorch gate order i,f,g,o

// ---------------- scratch (device globals: no cudaMalloc allowed) ----------
__device__ float g_xgates[(size_t)T_SEQ * BATCH * GATES];  // 256 MiB
__device__ float g_h[2][BATCH * HID];                      // double-buffered h
__device__ float g_c[BATCH * HID];

// ---------------- tf32 helpers --------------------------------------------
__device__ __forceinline__ uint32_t f2tf(float f) {
    uint32_t r;
    asm("cvt.rna.tf32.f32 %0, %1;" : "=r"(r) : "f"(f));
    return r;
}

// D = A(16x8, row) * B(8x8, col) + D, tf32 in / f32 accum
__device__ __forceinline__ void mma_tf32(float* d, const uint32_t* a, const uint32_t* b) {
    asm volatile(
        "mma.sync.aligned.m16n8k8.row.col.f32.tf32.tf32.f32 "
        "{%0,%1,%2,%3}, {%4,%5,%6,%7}, {%8,%9}, {%0,%1,%2,%3};\n"
        : "+f"(d[0]), "+f"(d[1]), "+f"(d[2]), "+f"(d[3])
        : "r"(a[0]), "r"(a[1]), "r"(a[2]), "r"(a[3]),
          "r"(b[0]), "r"(b[1]));
}

// ---------------- init: zero h0, c0 ----------------------------------------
__global__ void init_state() {
    int i = blockIdx.x * blockDim.x + threadIdx.x;
    if (i < BATCH * HID) {
        g_h[0][i] = 0.0f;
        g_c[i]    = 0.0f;
    }
}

// ---------------- input projection -----------------------------------------
// x_gates[row, col] = sum_k emb[x_seq[row], k] * W_ih[col, k] + b_ih[col] + b_hh[col]
// row = t*B + b  (16384 rows), col in [0, 4096)
// CTA tile 128(M) x 64(N), K-chunk 16. 256 threads = 8 warps (4m x 2n),
// warp tile 32x32 -> 2 m-frags x 4 n-frags of m16n8k8.
__global__ void __launch_bounds__(256)
input_gemm(const int* __restrict__ x_seq, const float* __restrict__ emb,
           const float* __restrict__ W_ih, const float* __restrict__ b_ih,
           const float* __restrict__ b_hh) {
    __shared__ uint32_t sA[128 * 20];   // [m][k], stride 20 (pad)
    __shared__ uint32_t sB[64 * 20];    // [n][k], stride 20
    __shared__ int stok[128];

    const int tid = threadIdx.x;
    const int bm = blockIdx.y;          // 0..127
    const int bn = blockIdx.x;          // 0..63

    if (tid < 128) stok[tid] = x_seq[bm * 128 + tid];
    __syncthreads();

    const int lane = tid & 31;
    const int w    = tid >> 5;
    const int wm   = w & 3;             // 0..3 -> m base wm*32
    const int wn   = w >> 2;            // 0..1 -> n base wn*32
    const int grp  = lane >> 2;         // groupID
    const int q4   = lane & 3;          // threadID_in_group

    float acc[2][4][4];
    #pragma unroll
    for (int i = 0; i < 2; i++)
        #pragma unroll
        for (int j = 0; j < 4; j++)
            #pragma unroll
            for (int r = 0; r < 4; r++) acc[i][j][r] = 0.0f;

    // staging (each thread: 2 A float4s + 1 B float4 per chunk)
    float4 ra0, ra1, rb;
    const int am0 = tid >> 2, akq = tid & 3;          // A elem 0: rows 0..63
    const int am1 = (tid + 256) >> 2;                 // A elem 1: rows 64..127
    const int bnn = tid >> 2, bkq = tid & 3;          // B: rows 0..63

    auto load_chunk = [&](int kb) {
        ra0 = *(const float4*)(emb + (size_t)stok[am0] * EMB + kb + akq * 4);
        ra1 = *(const float4*)(emb + (size_t)stok[am1] * EMB + kb + akq * 4);
        rb  = *(const float4*)(W_ih + (size_t)(bn * 64 + bnn) * EMB + kb + bkq * 4);
    };
    auto store_chunk = [&]() {
        uint32_t* pa0 = sA + am0 * 20 + akq * 4;
        pa0[0] = f2tf(ra0.x); pa0[1] = f2tf(ra0.y); pa0[2] = f2tf(ra0.z); pa0[3] = f2tf(ra0.w);
        uint32_t* pa1 = sA + am1 * 20 + akq * 4;
        pa1[0] = f2tf(ra1.x); pa1[1] = f2tf(ra1.y); pa1[2] = f2tf(ra1.z); pa1[3] = f2tf(ra1.w);
        uint32_t* pb = sB + bnn * 20 + bkq * 4;
        pb[0] = f2tf(rb.x); pb[1] = f2tf(rb.y); pb[2] = f2tf(rb.z); pb[3] = f2tf(rb.w);
    };
    auto compute = [&]() {
        #pragma unroll
        for (int ks = 0; ks < 2; ks++) {
            const int k0 = ks * 8;
            uint32_t af[2][4];
            #pragma unroll
            for (int fm = 0; fm < 2; fm++) {
                const int r = wm * 32 + fm * 16 + grp;
                af[fm][0] = sA[r * 20 + k0 + q4];
                af[fm][1] = sA[(r + 8) * 20 + k0 + q4];
                af[fm][2] = sA[r * 20 + k0 + q4 + 4];
                af[fm][3] = sA[(r + 8) * 20 + k0 + q4 + 4];
            }
            uint32_t bf[4][2];
            #pragma unroll
            for (int fn = 0; fn < 4; fn++) {
                const int c = wn * 32 + fn * 8 + grp;
                bf[fn][0] = sB[c * 20 + k0 + q4];
                bf[fn][1] = sB[c * 20 + k0 + q4 + 4];
            }
            #pragma unroll
            for (int fm = 0; fm < 2; fm++)
                #pragma unroll
                for (int fn = 0; fn < 4; fn++)
                    mma_tf32(acc[fm][fn], af[fm], bf[fn]);
        }
    };

    load_chunk(0);
    store_chunk();
    __syncthreads();
    for (int kb = 0; kb < EMB; kb += 16) {
        const bool more = (kb + 16) < EMB;
        if (more) load_chunk(kb + 16);
        compute();
        __syncthreads();
        if (more) { store_chunk(); __syncthreads(); }
    }

    // epilogue: + (b_ih + b_hh), write fp32
    #pragma unroll
    for (int fm = 0; fm < 2; fm++)
        #pragma unroll
        for (int fn = 0; fn < 4; fn++) {
            const int row = bm * 128 + wm * 32 + fm * 16 + grp;
            const int col = bn * 64 + wn * 32 + fn * 8 + q4 * 2;
            const float bi0 = b_ih[col] + b_hh[col];
            const float bi1 = b_ih[col + 1] + b_hh[col + 1];
            float* o0 = g_xgates + (size_t)row * GATES + col;
            o0[0] = acc[fm][fn][0] + bi0;
            o0[1] = acc[fm][fn][1] + bi1;
            float* o1 = g_xgates + (size_t)(row + 8) * GATES + col;
            o1[0] = acc[fm][fn][2] + bi0;
            o1[1] = acc[fm][fn][3] + bi1;
        }
}

// ---------------- one LSTM step ---------------------------------------------
// CTA owns 8 hidden columns (hj..hj+7) x all 4 gates x all 64 batches.
// GEMM tile: M=64 (batch) x N=32 (gate*8+hh) x K=1024.
// 256 threads = 8 warps (4m x 2n), warp tile 16x16 -> 1 a-frag, 2 n-frags.
// Fused epilogue: gates -> sigmoid/tanh -> c,h update -> outs[t].
__global__ void __launch_bounds__(256)
lstm_step(const float* __restrict__ W_hh, float* __restrict__ out, int t) {
    __shared__ uint32_t sA[64 * 20];    // h chunk [b][k]
    __shared__ uint32_t sB[32 * 20];    // W chunk [n][k]
    __shared__ float gbuf[64][33];      // gate pre-acts (h @ W_hh^T part)

    const float* __restrict__ h_in = g_h[t & 1];
    float* __restrict__ h_out      = g_h[(t + 1) & 1];

    const int tid = threadIdx.x;
    const int hj  = blockIdx.x * 8;     // hidden-slice base, 128 CTAs
    const int lane = tid & 31;
    const int w    = tid >> 5;
    const int wm   = w & 3;             // m base wm*16
    const int wn   = w >> 2;            // n base wn*16
    const int grp  = lane >> 2;
    const int q4   = lane & 3;

    float acc[2][4] = {{0.f,0.f,0.f,0.f},{0.f,0.f,0.f,0.f}};

    float4 ra, rb;
    const int am = tid >> 2, akq = tid & 3;          // A: 64 rows x 4 float4
    const int bnn = tid >> 2, bkq = tid & 3;         // B: 32 rows (tid < 128)
    const int wrow = (bnn >> 3) * HID + hj + (bnn & 7);  // gate*HID + hcol

    auto load_chunk = [&](int kb) {
        ra = *(const float4*)(h_in + am * HID + kb + akq * 4);
        if (tid < 128)
            rb = *(const float4*)(W_hh + (size_t)wrow * HID + kb + bkq * 4);
    };
    auto store_chunk = [&]() {
        uint32_t* pa = sA + am * 20 + akq * 4;
        pa[0] = f2tf(ra.x); pa[1] = f2tf(ra.y); pa[2] = f2tf(ra.z); pa[3] = f2tf(ra.w);
        if (tid < 128) {
            uint32_t* pb = sB + bnn * 20 + bkq * 4;
            pb[0] = f2tf(rb.x); pb[1] = f2tf(rb.y); pb[2] = f2tf(rb.z); pb[3] = f2tf(rb.w);
        }
    };
    auto compute = [&]() {
        #pragma unroll
        for (int ks = 0; ks < 2; ks++) {
            const int k0 = ks * 8;
            uint32_t af[4];
            const int r = wm * 16 + grp;
            af[0] = sA[r * 20 + k0 + q4];
            af[1] = sA[(r + 8) * 20 + k0 + q4];
            af[2] = sA[r * 20 + k0 + q4 + 4];
            af[3] = sA[(r + 8) * 20 + k0 + q4 + 4];
            #pragma unroll
            for (int fn = 0; fn < 2; fn++) {
                const int c = wn * 16 + fn * 8 + grp;
                uint32_t bf[2] = { sB[c * 20 + k0 + q4], sB[c * 20 + k0 + q4 + 4] };
                mma_tf32(acc[fn], af, bf);
            }
        }
    };

    load_chunk(0);
    store_chunk();
    __syncthreads();
    for (int kb = 0; kb < HID; kb += 16) {
        const bool more = (kb + 16) < HID;
        if (more) load_chunk(kb + 16);
        compute();
        __syncthreads();
        if (more) { store_chunk(); __syncthreads(); }
    }

    // park the recurrent-GEMM partials in smem
    #pragma unroll
    for (int fn = 0; fn < 2; fn++) {
        const int row = wm * 16 + grp;
        const int col = wn * 16 + fn * 8 + q4 * 2;
        gbuf[row][col]     = acc[fn][0];
        gbuf[row][col + 1] = acc[fn][1];
        gbuf[row + 8][col]     = acc[fn][2];
        gbuf[row + 8][col + 1] = acc[fn][3];
    }
    __syncthreads();

    // fused elementwise: 64 batches x 8 hidden cols = 512 items
    #pragma unroll
    for (int it = 0; it < 2; it++) {
        const int idx = tid + it * 256;
        const int b  = idx >> 3;
        const int hh = idx & 7;
        const int hcol = hj + hh;
        const float* xg = g_xgates + ((size_t)t * BATCH + b) * GATES;

        const float ip = gbuf[b][hh]      + xg[hcol];
        const float fp = gbuf[b][8 + hh]  + xg[HID + hcol];
        const float gp = gbuf[b][16 + hh] + xg[2 * HID + hcol];
        const float op = gbuf[b][24 + hh] + xg[3 * HID + hcol];

        const float ig = 1.0f / (1.0f + expf(-ip));
        const float fg = 1.0f / (1.0f + expf(-fp));
        const float gg = tanhf(gp);
        const float og = 1.0f / (1.0f + expf(-op));

        const float c_old = g_c[b * HID + hcol];
        const float c_new = fg * c_old + ig * gg;
        const float h_new = og * tanhf(c_new);

        g_c[b * HID + hcol]  = c_new;
        h_out[b * HID + hcol] = h_new;
        out[((size_t)t * BATCH + b) * HID + hcol] = h_new;
    }
}

// ---------------- finalize: append (h, c) after outs ------------------------
__global__ void finalize(float* __restrict__ out) {
    int i = blockIdx.x * blockDim.x + threadIdx.x;
    if (i < BATCH * HID) {
        // after 256 steps the final h lives in buffer (T_SEQ & 1) == 0
        out[(size_t)T_SEQ * BATCH * HID + i]               = g_h[0][i];
        out[(size_t)T_SEQ * BATCH * HID + BATCH * HID + i] = g_c[i];
    }
}

// ---------------- launch -----------------------------------------------------
extern "C" void kernel_launch(void* const* d_in, const int* in_sizes, int n_in,
                              void* d_out, int out_size) {
    const int*   x_seq = (const int*)d_in[0];
    const float* emb   = (const float*)d_in[1];
    const float* W_ih  = (const float*)d_in[2];
    const float* W_hh  = (const float*)d_in[3];
    const float* b_ih  = (const float*)d_in[4];
    const float* b_hh  = (const float*)d_in[5];
    float* out = (float*)d_out;

    init_state<<<(BATCH * HID + 255) / 256, 256>>>();

    dim3 ig_grid(GATES / 64, (T_SEQ * BATCH) / 128);   // (64, 128)
    input_gemm<<<ig_grid, 256>>>(x_seq, emb, W_ih, b_ih, b_hh);

    for (int t = 0; t < T_SEQ; t++)
        lstm_step<<<HID / 8, 256>>>(W_hh, out, t);

    finalize<<<(BATCH * HID + 255) / 256, 256>>>(out);
}

// round 2
// speedup vs baseline: 1.8370x; 1.8370x over previous
#include <cuda_runtime.h>
#include <cstdint>
#include <cmath>

#define T_SEQ 256
#define BATCH 64
#define EMB   512
#define HID   1024
#define GATES 4096   // 4*HID, gate order i,f,g,o

#define NCTA     128
#define NTHREADS 256
#define KCHUNK   64
#define NCHUNK   (HID / KCHUNK)        // 16
#define SW_STRIDE 1028                 // 1024 + 4 pad (conflict-free frag reads)
#define SA_STRIDE 68                   // 64 + 4 pad
#define SA_BUF    (64 * SA_STRIDE)     // words per A buffer
#define SMEM_WORDS (32 * SW_STRIDE + 3 * SA_BUF + 64 * 33)
#define SMEM_BYTES (SMEM_WORDS * 4)    // 192,256 B

// ---------------- scratch (device globals: no cudaMalloc allowed) ----------
__device__ __align__(16) float g_xgates[(size_t)T_SEQ * BATCH * GATES];
__device__ __align__(16) float g_h[2][BATCH * HID];   // tf32 bit patterns
__device__ __align__(16) float g_c[BATCH * HID];
__device__ unsigned g_bar;                            // monotonic grid barrier

// ---------------- tf32 / mma helpers --------------------------------------
__device__ __forceinline__ uint32_t f2tf(float f) {
    uint32_t r;
    asm("cvt.rna.tf32.f32 %0, %1;" : "=r"(r) : "f"(f));
    return r;
}

__device__ __forceinline__ void mma_tf32(float* d, const uint32_t* a, const uint32_t* b) {
    asm volatile(
        "mma.sync.aligned.m16n8k8.row.col.f32.tf32.tf32.f32 "
        "{%0,%1,%2,%3}, {%4,%5,%6,%7}, {%8,%9}, {%0,%1,%2,%3};\n"
        : "+f"(d[0]), "+f"(d[1]), "+f"(d[2]), "+f"(d[3])
        : "r"(a[0]), "r"(a[1]), "r"(a[2]), "r"(a[3]),
          "r"(b[0]), "r"(b[1]));
}

__device__ __forceinline__ void cp_async16(uint32_t saddr, const void* gaddr) {
    asm volatile("cp.async.cg.shared.global [%0], [%1], 16;\n" :: "r"(saddr), "l"(gaddr));
}
__device__ __forceinline__ void cp_commit() { asm volatile("cp.async.commit_group;\n"); }
__device__ __forceinline__ void cp_wait0()  { asm volatile("cp.async.wait_group 0;\n"); }
__device__ __forceinline__ void cp_wait1()  { asm volatile("cp.async.wait_group 1;\n"); }

// ---------------- init: zero h0, c0 ----------------------------------------
__global__ void init_state() {
    int i = blockIdx.x * blockDim.x + threadIdx.x;
    if (i < BATCH * HID) {
        g_h[0][i] = 0.0f;   // tf32 zero == fp32 zero
        g_c[i]    = 0.0f;
    }
}

// ---------------- input projection (unchanged from R1) ---------------------
__global__ void __launch_bounds__(256)
input_gemm(const int* __restrict__ x_seq, const float* __restrict__ emb,
           const float* __restrict__ W_ih, const float* __restrict__ b_ih,
           const float* __restrict__ b_hh) {
    __shared__ uint32_t sA[128 * 20];
    __shared__ uint32_t sB[64 * 20];
    __shared__ int stok[128];

    const int tid = threadIdx.x;
    const int bm = blockIdx.y;
    const int bn = blockIdx.x;

    if (tid < 128) stok[tid] = x_seq[bm * 128 + tid];
    __syncthreads();

    const int lane = tid & 31;
    const int w    = tid >> 5;
    const int wm   = w & 3;
    const int wn   = w >> 2;
    const int grp  = lane >> 2;
    const int q4   = lane & 3;

    float acc[2][4][4];
    #pragma unroll
    for (int i = 0; i < 2; i++)
        #pragma unroll
        for (int j = 0; j < 4; j++)
            #pragma unroll
            for (int r = 0; r < 4; r++) acc[i][j][r] = 0.0f;

    float4 ra0, ra1, rb;
    const int am0 = tid >> 2, akq = tid & 3;
    const int am1 = (tid + 256) >> 2;
    const int bnn = tid >> 2, bkq = tid & 3;

    auto load_chunk = [&](int kb) {
        ra0 = *(const float4*)(emb + (size_t)stok[am0] * EMB + kb + akq * 4);
        ra1 = *(const float4*)(emb + (size_t)stok[am1] * EMB + kb + akq * 4);
        rb  = *(const float4*)(W_ih + (size_t)(bn * 64 + bnn) * EMB + kb + bkq * 4);
    };
    auto store_chunk = [&]() {
        uint32_t* pa0 = sA + am0 * 20 + akq * 4;
        pa0[0] = f2tf(ra0.x); pa0[1] = f2tf(ra0.y); pa0[2] = f2tf(ra0.z); pa0[3] = f2tf(ra0.w);
        uint32_t* pa1 = sA + am1 * 20 + akq * 4;
        pa1[0] = f2tf(ra1.x); pa1[1] = f2tf(ra1.y); pa1[2] = f2tf(ra1.z); pa1[3] = f2tf(ra1.w);
        uint32_t* pb = sB + bnn * 20 + bkq * 4;
        pb[0] = f2tf(rb.x); pb[1] = f2tf(rb.y); pb[2] = f2tf(rb.z); pb[3] = f2tf(rb.w);
    };
    auto compute = [&]() {
        #pragma unroll
        for (int ks = 0; ks < 2; ks++) {
            const int k0 = ks * 8;
            uint32_t af[2][4];
            #pragma unroll
            for (int fm = 0; fm < 2; fm++) {
                const int r = wm * 32 + fm * 16 + grp;
                af[fm][0] = sA[r * 20 + k0 + q4];
                af[fm][1] = sA[(r + 8) * 20 + k0 + q4];
                af[fm][2] = sA[r * 20 + k0 + q4 + 4];
                af[fm][3] = sA[(r + 8) * 20 + k0 + q4 + 4];
            }
            uint32_t bf[4][2];
            #pragma unroll
            for (int fn = 0; fn < 4; fn++) {
                const int c = wn * 32 + fn * 8 + grp;
                bf[fn][0] = sB[c * 20 + k0 + q4];
                bf[fn][1] = sB[c * 20 + k0 + q4 + 4];
            }
            #pragma unroll
            for (int fm = 0; fm < 2; fm++)
                #pragma unroll
                for (int fn = 0; fn < 4; fn++)
                    mma_tf32(acc[fm][fn], af[fm], bf[fn]);
        }
    };

    load_chunk(0);
    store_chunk();
    __syncthreads();
    for (int kb = 0; kb < EMB; kb += 16) {
        const bool more = (kb + 16) < EMB;
        if (more) load_chunk(kb + 16);
        compute();
        __syncthreads();
        if (more) { store_chunk(); __syncthreads(); }
    }

    #pragma unroll
    for (int fm = 0; fm < 2; fm++)
        #pragma unroll
        for (int fn = 0; fn < 4; fn++) {
            const int row = bm * 128 + wm * 32 + fm * 16 + grp;
            const int col = bn * 64 + wn * 32 + fn * 8 + q4 * 2;
            const float bi0 = b_ih[col] + b_hh[col];
            const float bi1 = b_ih[col + 1] + b_hh[col + 1];
            float* o0 = g_xgates + (size_t)row * GATES + col;
            o0[0] = acc[fm][fn][0] + bi0;
            o0[1] = acc[fm][fn][1] + bi1;
            float* o1 = g_xgates + (size_t)(row + 8) * GATES + col;
            o1[0] = acc[fm][fn][2] + bi0;
            o1[1] = acc[fm][fn][3] + bi1;
        }
}

// ---------------- persistent recurrence -------------------------------------
// 128 CTAs (one per SM, co-resident). CTA b owns hidden cols [8b, 8b+8) for
// all 4 gates (N=32 rows of W_hh), W slice resident in smem as tf32.
// Per step: GEMM M=64(batch) x N=32 x K=1024 with triple-buffered cp.async
// A-pipeline; fused gate epilogue; software grid barrier.
__global__ void __launch_bounds__(NTHREADS, 1)
lstm_persistent(const float* __restrict__ W_hh, float* __restrict__ out) {
    extern __shared__ uint32_t smem[];
    uint32_t* sW  = smem;                         // 32 x SW_STRIDE
    uint32_t* sA  = smem + 32 * SW_STRIDE;        // 3 x 64 x SA_STRIDE
    float*    gbuf = (float*)(sA + 3 * SA_BUF);   // 64 x 33

    const int tid  = threadIdx.x;
    const int hj   = blockIdx.x * 8;
    const int lane = tid & 31;
    const int w    = tid >> 5;
    const int wm   = w & 3;          // m base wm*16
    const int wn   = w >> 2;         // n base wn*16
    const int grp  = lane >> 2;
    const int q4   = lane & 3;

    // ---- one-time: load + convert W slice (32 rows x 1024) to smem tf32 ----
    for (int it = tid; it < 32 * 256; it += NTHREADS) {
        const int n  = it >> 8;       // local row 0..31  (gate = n>>3, col = n&7)
        const int f4 = it & 255;      // float4 index within row
        const float4 v = *(const float4*)(
            W_hh + (size_t)((n >> 3) * HID + hj + (n & 7)) * HID + f4 * 4);
        uint32_t* p = sW + n * SW_STRIDE + f4 * 4;
        p[0] = f2tf(v.x); p[1] = f2tf(v.y); p[2] = f2tf(v.z); p[3] = f2tf(v.w);
    }
    __syncthreads();

    const uint32_t sa_base = (uint32_t)__cvta_generic_to_shared(sA);
    const int ar = tid >> 2;              // A row 0..63
    const int ac = (tid & 3) * 16;        // word base within chunk (4 float4s)

    for (int t = 0; t < T_SEQ; t++) {
        const float* __restrict__ h_in  = g_h[t & 1];        // tf32 bits
        float* __restrict__       h_out = g_h[(t + 1) & 1];

        float acc[2][4] = {{0.f,0.f,0.f,0.f},{0.f,0.f,0.f,0.f}};

        auto issue = [&](int c) {
            const int buf = c % 3;
            const float* src = h_in + (size_t)ar * HID + c * KCHUNK + ac;
            const uint32_t dst = sa_base + (buf * SA_BUF + ar * SA_STRIDE + ac) * 4;
            #pragma unroll
            for (int j = 0; j < 4; j++)
                cp_async16(dst + j * 16, src + j * 4);
            cp_commit();
        };

        issue(0);
        for (int c = 0; c < NCHUNK; c++) {
            if (c + 1 < NCHUNK) { issue(c + 1); cp_wait1(); }
            else                { cp_wait0(); }
            __syncthreads();

            const uint32_t* A = sA + (c % 3) * SA_BUF;
            const int kb = c * KCHUNK;
            #pragma unroll
            for (int ks = 0; ks < KCHUNK / 8; ks++) {
                const int k0 = ks * 8;
                uint32_t af[4];
                const int r = wm * 16 + grp;
                af[0] = A[r * SA_STRIDE + k0 + q4];
                af[1] = A[(r + 8) * SA_STRIDE + k0 + q4];
                af[2] = A[r * SA_STRIDE + k0 + q4 + 4];
                af[3] = A[(r + 8) * SA_STRIDE + k0 + q4 + 4];
                #pragma unroll
                for (int fn = 0; fn < 2; fn++) {
                    const int cc = wn * 16 + fn * 8 + grp;
                    uint32_t bf[2] = { sW[cc * SW_STRIDE + kb + k0 + q4],
                                       sW[cc * SW_STRIDE + kb + k0 + q4 + 4] };
                    mma_tf32(acc[fn], af, bf);
                }
            }
        }

        // park recurrent-GEMM partials
        #pragma unroll
        for (int fn = 0; fn < 2; fn++) {
            const int row = wm * 16 + grp;
            const int col = wn * 16 + fn * 8 + q4 * 2;
            gbuf[row * 33 + col]           = acc[fn][0];
            gbuf[row * 33 + col + 1]       = acc[fn][1];
            gbuf[(row + 8) * 33 + col]     = acc[fn][2];
            gbuf[(row + 8) * 33 + col + 1] = acc[fn][3];
        }
        __syncthreads();

        // fused elementwise: 64 batches x 8 hidden cols
        #pragma unroll
        for (int it2 = 0; it2 < 2; it2++) {
            const int idx  = tid + it2 * NTHREADS;
            const int b    = idx >> 3;
            const int hh   = idx & 7;
            const int hcol = hj + hh;
            const float* xg = g_xgates + ((size_t)t * BATCH + b) * GATES;

            const float ip = gbuf[b * 33 + hh]      + xg[hcol];
            const float fp = gbuf[b * 33 + 8 + hh]  + xg[HID + hcol];
            const float gp = gbuf[b * 33 + 16 + hh] + xg[2 * HID + hcol];
            const float op = gbuf[b * 33 + 24 + hh] + xg[3 * HID + hcol];

            const float ig = 1.0f / (1.0f + expf(-ip));
            const float fg = 1.0f / (1.0f + expf(-fp));
            const float gg = tanhf(gp);
            const float og = 1.0f / (1.0f + expf(-op));

            const float c_old = g_c[b * HID + hcol];
            const float c_new = fg * c_old + ig * gg;
            const float h_new = og * tanhf(c_new);

            g_c[b * HID + hcol]   = c_new;
            h_out[b * HID + hcol] = __uint_as_float(f2tf(h_new));  // pre-truncate for next GEMM
            out[((size_t)t * BATCH + b) * HID + hcol] = h_new;     // full-precision output
        }

        // ---- grid barrier (release/acquire, wrap-safe, monotonic counter) ----
        __syncthreads();
        if (tid == 0) {
            __threadfence();
            unsigned old;
            asm volatile("atom.add.release.gpu.global.u32 %0, [%1], 1;"
                         : "=r"(old) : "l"(&g_bar) : "memory");
            const unsigned target = old - (old % NCTA) + NCTA;
            unsigned cur;
            do {
                asm volatile("ld.acquire.gpu.global.u32 %0, [%1];"
                             : "=r"(cur) : "l"(&g_bar) : "memory");
            } while ((int)(cur - target) < 0);
        }
        __syncthreads();
    }
}

// ---------------- finalize: append (h, c) after outs ------------------------
__global__ void finalize(float* __restrict__ out) {
    int i = blockIdx.x * blockDim.x + threadIdx.x;
    if (i < BATCH * HID) {
        // final h == outs[T-1] (full fp32, not tf32-truncated)
        out[(size_t)T_SEQ * BATCH * HID + i] =
            out[(size_t)(T_SEQ - 1) * BATCH * HID + i];
        out[(size_t)T_SEQ * BATCH * HID + BATCH * HID + i] = g_c[i];
    }
}

// ---------------- launch -----------------------------------------------------
extern "C" void kernel_launch(void* const* d_in, const int* in_sizes, int n_in,
                              void* d_out, int out_size) {
    const int*   x_seq = (const int*)d_in[0];
    const float* emb   = (const float*)d_in[1];
    const float* W_ih  = (const float*)d_in[2];
    const float* W_hh  = (const float*)d_in[3];
    const float* b_ih  = (const float*)d_in[4];
    const float* b_hh  = (const float*)d_in[5];
    float* out = (float*)d_out;

    cudaFuncSetAttribute(lstm_persistent,
                         cudaFuncAttributeMaxDynamicSharedMemorySize, SMEM_BYTES);

    init_state<<<(BATCH * HID + 255) / 256, 256>>>();

    dim3 ig_grid(GATES / 64, (T_SEQ * BATCH) / 128);   // (64, 128)
    input_gemm<<<ig_grid, 256>>>(x_seq, emb, W_ih, b_ih, b_hh);

    lstm_persistent<<<NCTA, NTHREADS, SMEM_BYTES>>>(W_hh, out);

    finalize<<<(BATCH * HID + 255) / 256, 256>>>(out);
}

// round 4
// speedup vs baseline: 3.2239x; 1.7550x over previous
#include <cuda_runtime.h>
#include <cuda_fp16.h>
#include <cstdint>
#include <cmath>

#define T_SEQ 256
#define BATCH 64
#define EMB   512
#define HID   1024
#define GATES 4096   // 4*HID, gate order i,f,g,o

#define NCTA     128
#define NTHREADS 256

// ---- persistent-kernel smem layout ----
// W: 32 rows x 1024 halfs, row stride 516 words (1032 halfs, pad 4 words)
// A: 3 chunk buffers, each 64 rows x 256 halfs, row stride 132 words
#define SW_STRIDE 516                    // uint32 words per W row
#define SA_STRIDE 132                    // uint32 words per A row per chunk
#define SA_BUF_W  (64 * SA_STRIDE)       // words per A buffer
#define SMO_W     64
#define SMO_A     (SMO_W + 32 * SW_STRIDE * 4)           // 66112
#define SMO_GBUF  (SMO_A + 3 * SA_BUF_W * 4)             // 167488
#define SMEM_BYTES (SMO_GBUF + 64 * 33 * 4)              // 175936

// ---------------- scratch (device globals) ---------------------------------
__device__ __align__(16) float  g_xgates[(size_t)T_SEQ * BATCH * GATES];
__device__ __align__(16) __half g_h[2][BATCH * HID];
__device__ __align__(16) float  g_c[BATCH * HID];
__device__ unsigned g_bar;

// ---------------- helpers ---------------------------------------------------
__device__ __forceinline__ uint32_t f2tf(float f) {
    uint32_t r;
    asm("cvt.rna.tf32.f32 %0, %1;" : "=r"(r) : "f"(f));
    return r;
}

// tf32 m16n8k8 (input_gemm only)
__device__ __forceinline__ void mma_tf32(float* d, const uint32_t* a, const uint32_t* b) {
    asm volatile(
        "mma.sync.aligned.m16n8k8.row.col.f32.tf32.tf32.f32 "
        "{%0,%1,%2,%3}, {%4,%5,%6,%7}, {%8,%9}, {%0,%1,%2,%3};\n"
        : "+f"(d[0]), "+f"(d[1]), "+f"(d[2]), "+f"(d[3])
        : "r"(a[0]), "r"(a[1]), "r"(a[2]), "r"(a[3]),
          "r"(b[0]), "r"(b[1]));
}

// fp16 m16n8k16, fp32 accum (recurrence)
__device__ __forceinline__ void mma_f16(float* d, const uint32_t* a, uint32_t b0, uint32_t b1) {
    asm volatile(
        "mma.sync.aligned.m16n8k16.row.col.f32.f16.f16.f32 "
        "{%0,%1,%2,%3}, {%4,%5,%6,%7}, {%8,%9}, {%0,%1,%2,%3};\n"
        : "+f"(d[0]), "+f"(d[1]), "+f"(d[2]), "+f"(d[3])
        : "r"(a[0]), "r"(a[1]), "r"(a[2]), "r"(a[3]),
          "r"(b0), "r"(b1));
}

__device__ __forceinline__ void cp_async16(uint32_t saddr, const void* gaddr) {
    asm volatile("cp.async.cg.shared.global [%0], [%1], 16;\n" :: "r"(saddr), "l"(gaddr));
}
__device__ __forceinline__ void cp_commit() { asm volatile("cp.async.commit_group;\n"); }
__device__ __forceinline__ void cp_wait0()  { asm volatile("cp.async.wait_group 0;\n"); }
__device__ __forceinline__ void cp_wait1()  { asm volatile("cp.async.wait_group 1;\n"); }

__device__ __forceinline__ uint32_t smem_u32(const void* p) {
    return (uint32_t)__cvta_generic_to_shared(p);
}

// ---------------- init: zero h0, c0 ----------------------------------------
__global__ void init_state() {
    int i = blockIdx.x * blockDim.x + threadIdx.x;
    if (i < BATCH * HID) {
        g_h[0][i] = __float2half(0.0f);
        g_c[i]    = 0.0f;
    }
}

// ---------------- input projection (unchanged, tf32) ------------------------
__global__ void __launch_bounds__(256)
input_gemm(const int* __restrict__ x_seq, const float* __restrict__ emb,
           const float* __restrict__ W_ih, const float* __restrict__ b_ih,
           const float* __restrict__ b_hh) {
    __shared__ uint32_t sA[128 * 20];
    __shared__ uint32_t sB[64 * 20];
    __shared__ int stok[128];

    const int tid = threadIdx.x;
    const int bm = blockIdx.y;
    const int bn = blockIdx.x;

    if (tid < 128) stok[tid] = x_seq[bm * 128 + tid];
    __syncthreads();

    const int lane = tid & 31;
    const int w    = tid >> 5;
    const int wm   = w & 3;
    const int wn   = w >> 2;
    const int grp  = lane >> 2;
    const int q4   = lane & 3;

    float acc[2][4][4];
    #pragma unroll
    for (int i = 0; i < 2; i++)
        #pragma unroll
        for (int j = 0; j < 4; j++)
            #pragma unroll
            for (int r = 0; r < 4; r++) acc[i][j][r] = 0.0f;

    float4 ra0, ra1, rb;
    const int am0 = tid >> 2, akq = tid & 3;
    const int am1 = (tid + 256) >> 2;
    const int bnn = tid >> 2, bkq = tid & 3;

    auto load_chunk = [&](int kb) {
        ra0 = *(const float4*)(emb + (size_t)stok[am0] * EMB + kb + akq * 4);
        ra1 = *(const float4*)(emb + (size_t)stok[am1] * EMB + kb + akq * 4);
        rb  = *(const float4*)(W_ih + (size_t)(bn * 64 + bnn) * EMB + kb + bkq * 4);
    };
    auto store_chunk = [&]() {
        uint32_t* pa0 = sA + am0 * 20 + akq * 4;
        pa0[0] = f2tf(ra0.x); pa0[1] = f2tf(ra0.y); pa0[2] = f2tf(ra0.z); pa0[3] = f2tf(ra0.w);
        uint32_t* pa1 = sA + am1 * 20 + akq * 4;
        pa1[0] = f2tf(ra1.x); pa1[1] = f2tf(ra1.y); pa1[2] = f2tf(ra1.z); pa1[3] = f2tf(ra1.w);
        uint32_t* pb = sB + bnn * 20 + bkq * 4;
        pb[0] = f2tf(rb.x); pb[1] = f2tf(rb.y); pb[2] = f2tf(rb.z); pb[3] = f2tf(rb.w);
    };
    auto compute = [&]() {
        #pragma unroll
        for (int ks = 0; ks < 2; ks++) {
            const int k0 = ks * 8;
            uint32_t af[2][4];
            #pragma unroll
            for (int fm = 0; fm < 2; fm++) {
                const int r = wm * 32 + fm * 16 + grp;
                af[fm][0] = sA[r * 20 + k0 + q4];
                af[fm][1] = sA[(r + 8) * 20 + k0 + q4];
                af[fm][2] = sA[r * 20 + k0 + q4 + 4];
                af[fm][3] = sA[(r + 8) * 20 + k0 + q4 + 4];
            }
            uint32_t bf[4][2];
            #pragma unroll
            for (int fn = 0; fn < 4; fn++) {
                const int c = wn * 32 + fn * 8 + grp;
                bf[fn][0] = sB[c * 20 + k0 + q4];
                bf[fn][1] = sB[c * 20 + k0 + q4 + 4];
            }
            #pragma unroll
            for (int fm = 0; fm < 2; fm++)
                #pragma unroll
                for (int fn = 0; fn < 4; fn++)
                    mma_tf32(acc[fm][fn], af[fm], bf[fn]);
        }
    };

    load_chunk(0);
    store_chunk();
    __syncthreads();
    for (int kb = 0; kb < EMB; kb += 16) {
        const bool more = (kb + 16) < EMB;
        if (more) load_chunk(kb + 16);
        compute();
        __syncthreads();
        if (more) { store_chunk(); __syncthreads(); }
    }

    #pragma unroll
    for (int fm = 0; fm < 2; fm++)
        #pragma unroll
        for (int fn = 0; fn < 4; fn++) {
            const int row = bm * 128 + wm * 32 + fm * 16 + grp;
            const int col = bn * 64 + wn * 32 + fn * 8 + q4 * 2;
            const float bi0 = b_ih[col] + b_hh[col];
            const float bi1 = b_ih[col + 1] + b_hh[col + 1];
            float* o0 = g_xgates + (size_t)row * GATES + col;
            o0[0] = acc[fm][fn][0] + bi0;
            o0[1] = acc[fm][fn][1] + bi1;
            float* o1 = g_xgates + (size_t)(row + 8) * GATES + col;
            o1[0] = acc[fm][fn][2] + bi0;
            o1[1] = acc[fm][fn][3] + bi1;
        }
}

// ---------------- persistent recurrence (fp16 MMA) --------------------------
// 128 CTAs, 1/SM. CTA owns hidden cols [8b, 8b+8) x 4 gates = N=32 rows of W,
// resident in smem as fp16. Per step: GEMM M=64(batch) x N=32 x K=1024 in
// 4 chunks of K=256 (fp16), triple-buffered cp.async, one sync per chunk;
// fused gate epilogue; software grid barrier.
__global__ void __launch_bounds__(NTHREADS, 1)
lstm_persistent(const float* __restrict__ W_hh, float* __restrict__ out) {
    extern __shared__ char smem[];
    const uint32_t smb = smem_u32(smem);
    uint32_t* sW   = (uint32_t*)(smem + SMO_W);
    uint32_t* sAw  = (uint32_t*)(smem + SMO_A);
    float*    gbuf = (float*)(smem + SMO_GBUF);

    const int tid  = threadIdx.x;
    const int hj   = blockIdx.x * 8;
    const int lane = tid & 31;
    const int w    = tid >> 5;
    const int wm   = w & 3;          // m base wm*16
    const int wn   = w >> 2;         // n base wn*16
    const int grp  = lane >> 2;
    const int q4   = lane & 3;

    // ---- one-time: W slice (32 x 1024) -> smem fp16 ----
    for (int it = tid; it < 32 * 512; it += NTHREADS) {
        const int n  = it >> 9;          // N-row: gate = n>>3, hcol = n&7
        const int w2 = it & 511;         // half2 index within row
        const float2 v = *(const float2*)(
            W_hh + (size_t)((n >> 3) * HID + hj + (n & 7)) * HID + w2 * 2);
        __half2 hv = __floats2half2_rn(v.x, v.y);
        sW[n * SW_STRIDE + w2] = *(uint32_t*)&hv;
    }
    __syncthreads();

    // cp.async one K=256-half chunk of h into buffer (c % 3)
    auto fill = [&](const __half* h_in, int c) {
        const int buf = c % 3;
        #pragma unroll
        for (int j = 0; j < 8; j++) {
            const int gi = tid + j * NTHREADS;   // 0..2047
            const int b  = gi >> 5;              // batch row
            const int g  = gi & 31;              // 16B granule (8 halfs)
            cp_async16(smb + SMO_A + (buf * SA_BUF_W + b * SA_STRIDE + g * 4) * 4,
                       h_in + (size_t)b * HID + c * 256 + g * 8);
        }
        cp_commit();
    };

    for (int t = 0; t < T_SEQ; t++) {
        const __half* __restrict__ h_in  = g_h[t & 1];
        __half* __restrict__       h_out = g_h[(t + 1) & 1];

        float acc[2][4] = {{0.f,0.f,0.f,0.f},{0.f,0.f,0.f,0.f}};

        fill(h_in, 0);
        #pragma unroll
        for (int c = 0; c < 4; c++) {
            if (c < 3) { fill(h_in, c + 1); cp_wait1(); }
            else       { cp_wait0(); }
            __syncthreads();

            const uint32_t* A = sAw + (c % 3) * SA_BUF_W;
            #pragma unroll
            for (int ksl = 0; ksl < 16; ksl++) {
                const int r = wm * 16 + grp;
                uint32_t af[4];
                af[0] = A[r * SA_STRIDE + ksl * 8 + q4];
                af[1] = A[(r + 8) * SA_STRIDE + ksl * 8 + q4];
                af[2] = A[r * SA_STRIDE + ksl * 8 + q4 + 4];
                af[3] = A[(r + 8) * SA_STRIDE + ksl * 8 + q4 + 4];
                const int kw = (c * 16 + ksl) * 8;
                #pragma unroll
                for (int fn = 0; fn < 2; fn++) {
                    const int n = wn * 16 + fn * 8 + grp;
                    mma_f16(acc[fn], af,
                            sW[n * SW_STRIDE + kw + q4],
                            sW[n * SW_STRIDE + kw + q4 + 4]);
                }
            }
        }

        // park recurrent-GEMM partials
        #pragma unroll
        for (int fn = 0; fn < 2; fn++) {
            const int row = wm * 16 + grp;
            const int col = wn * 16 + fn * 8 + q4 * 2;
            gbuf[row * 33 + col]           = acc[fn][0];
            gbuf[row * 33 + col + 1]       = acc[fn][1];
            gbuf[(row + 8) * 33 + col]     = acc[fn][2];
            gbuf[(row + 8) * 33 + col + 1] = acc[fn][3];
        }
        __syncthreads();

        // fused elementwise: 64 batches x 8 hidden cols
        #pragma unroll
        for (int it2 = 0; it2 < 2; it2++) {
            const int idx  = tid + it2 * NTHREADS;
            const int b    = idx >> 3;
            const int hh   = idx & 7;
            const int hcol = hj + hh;
            const float* xg = g_xgates + ((size_t)t * BATCH + b) * GATES;

            const float ip = gbuf[b * 33 + hh]      + xg[hcol];
            const float fp = gbuf[b * 33 + 8 + hh]  + xg[HID + hcol];
            const float gp = gbuf[b * 33 + 16 + hh] + xg[2 * HID + hcol];
            const float op = gbuf[b * 33 + 24 + hh] + xg[3 * HID + hcol];

            const float ig = 1.0f / (1.0f + expf(-ip));
            const float fg = 1.0f / (1.0f + expf(-fp));
            const float gg = tanhf(gp);
            const float og = 1.0f / (1.0f + expf(-op));

            const float c_old = g_c[b * HID + hcol];
            const float c_new = fg * c_old + ig * gg;
            const float h_new = og * tanhf(c_new);

            g_c[b * HID + hcol]   = c_new;
            h_out[b * HID + hcol] = __float2half_rn(h_new);
            out[((size_t)t * BATCH + b) * HID + hcol] = h_new;
        }

        // ---- grid barrier (release/acquire, wrap-safe) ----
        __syncthreads();
        if (tid == 0) {
            __threadfence();
            unsigned old;
            asm volatile("atom.add.release.gpu.global.u32 %0, [%1], 1;"
                         : "=r"(old) : "l"(&g_bar) : "memory");
            const unsigned target = old - (old % NCTA) + NCTA;
            unsigned cur;
            do {
                asm volatile("ld.acquire.gpu.global.u32 %0, [%1];"
                             : "=r"(cur) : "l"(&g_bar) : "memory");
            } while ((int)(cur - target) < 0);
        }
        __syncthreads();
    }
}

// ---------------- finalize: append (h, c) after outs ------------------------
__global__ void finalize(float* __restrict__ out) {
    int i = blockIdx.x * blockDim.x + threadIdx.x;
    if (i < BATCH * HID) {
        out[(size_t)T_SEQ * BATCH * HID + i] =
            out[(size_t)(T_SEQ - 1) * BATCH * HID + i];
        out[(size_t)T_SEQ * BATCH * HID + BATCH * HID + i] = g_c[i];
    }
}

// ---------------- launch -----------------------------------------------------
extern "C" void kernel_launch(void* const* d_in, const int* in_sizes, int n_in,
                              void* d_out, int out_size) {
    const int*   x_seq = (const int*)d_in[0];
    const float* emb   = (const float*)d_in[1];
    const float* W_ih  = (const float*)d_in[2];
    const float* W_hh  = (const float*)d_in[3];
    const float* b_ih  = (const float*)d_in[4];
    const float* b_hh  = (const float*)d_in[5];
    float* out = (float*)d_out;

    cudaFuncSetAttribute(lstm_persistent,
                         cudaFuncAttributeMaxDynamicSharedMemorySize, SMEM_BYTES);

    init_state<<<(BATCH * HID + 255) / 256, 256>>>();

    dim3 ig_grid(GATES / 64, (T_SEQ * BATCH) / 128);   // (64, 128)
    input_gemm<<<ig_grid, 256>>>(x_seq, emb, W_ih, b_ih, b_hh);

    lstm_persistent<<<NCTA, NTHREADS, SMEM_BYTES>>>(W_hh, out);

    finalize<<<(BATCH * HID + 255) / 256, 256>>>(out);
}

// round 5
// speedup vs baseline: 4.2136x; 1.3070x over previous
#include <cuda_runtime.h>
#include <cuda_fp16.h>
#include <cstdint>
#include <cmath>

#define T_SEQ 256
#define BATCH 64
#define EMB   512
#define HID   1024
#define GATES 4096   // 4*HID, gate order i,f,g,o

#define NCTA     128
#define NTHREADS 256

// ---- persistent-kernel smem layout ----
#define SW_STRIDE 516                    // uint32 words per W row (1032 halfs)
#define SA_STRIDE 132                    // uint32 words per A row per chunk
#define SA_BUF_W  (64 * SA_STRIDE)
#define SMO_W     64
#define SMO_A     (SMO_W + 32 * SW_STRIDE * 4)
#define SMO_GBUF  (SMO_A + 3 * SA_BUF_W * 4)
#define SMEM_BYTES (SMO_GBUF + 64 * 33 * 4)              // 175936

// ---------------- scratch (device globals) ---------------------------------
__device__ __align__(16) float  g_xgates[(size_t)T_SEQ * BATCH * GATES];
__device__ __align__(16) __half g_h[2][BATCH * HID];
__device__ __align__(16) float  g_c[BATCH * HID];
__device__ unsigned g_bar;

// ---------------- helpers ---------------------------------------------------
// fp16 m16n8k16, fp32 accum
__device__ __forceinline__ void mma_f16(float* d, const uint32_t* a, uint32_t b0, uint32_t b1) {
    asm volatile(
        "mma.sync.aligned.m16n8k16.row.col.f32.f16.f16.f32 "
        "{%0,%1,%2,%3}, {%4,%5,%6,%7}, {%8,%9}, {%0,%1,%2,%3};\n"
        : "+f"(d[0]), "+f"(d[1]), "+f"(d[2]), "+f"(d[3])
        : "r"(a[0]), "r"(a[1]), "r"(a[2]), "r"(a[3]),
          "r"(b0), "r"(b1));
}

__device__ __forceinline__ void cp_async16(uint32_t saddr, const void* gaddr) {
    asm volatile("cp.async.cg.shared.global [%0], [%1], 16;\n" :: "r"(saddr), "l"(gaddr));
}
__device__ __forceinline__ void cp_commit() { asm volatile("cp.async.commit_group;\n"); }
__device__ __forceinline__ void cp_wait0()  { asm volatile("cp.async.wait_group 0;\n"); }
__device__ __forceinline__ void cp_wait1()  { asm volatile("cp.async.wait_group 1;\n"); }

__device__ __forceinline__ uint32_t smem_u32(const void* p) {
    return (uint32_t)__cvta_generic_to_shared(p);
}

__device__ __forceinline__ uint32_t pack_h2(float x, float y) {
    __half2 hv = __floats2half2_rn(x, y);
    return *(uint32_t*)&hv;
}

// ---------------- init: zero h0, c0 ----------------------------------------
__global__ void init_state() {
    int i = blockIdx.x * blockDim.x + threadIdx.x;
    if (i < BATCH * HID) {
        g_h[0][i] = __float2half(0.0f);
        g_c[i]    = 0.0f;
    }
}

// ---------------- input projection (fp16, 128x128 tile) ---------------------
// x_gates[row, col] = sum_k emb[x_seq[row], k] * W_ih[col, k] + b_ih[col] + b_hh[col]
// CTA tile 128(M) x 128(N), K-chunk 32 (2 x k16). 256 threads = 8 warps
// (4m x 2n); warp tile 32m x 64n -> 2 m-frags x 8 n-frags.
__global__ void __launch_bounds__(256)
input_gemm(const int* __restrict__ x_seq, const float* __restrict__ emb,
           const float* __restrict__ W_ih, const float* __restrict__ b_ih,
           const float* __restrict__ b_hh) {
    __shared__ uint32_t sA[128 * 20];   // [m][k-words], stride 20 (16 + 4 pad)
    __shared__ uint32_t sB[128 * 20];   // [n][k-words]
    __shared__ int stok[128];

    const int tid = threadIdx.x;
    const int bm = blockIdx.y;          // 0..127
    const int bn = blockIdx.x;          // 0..31

    if (tid < 128) stok[tid] = x_seq[bm * 128 + tid];
    __syncthreads();

    const int lane = tid & 31;
    const int w    = tid >> 5;
    const int wm   = w & 3;             // m base wm*32
    const int wn   = w >> 2;            // n base wn*64
    const int grp  = lane >> 2;
    const int q4   = lane & 3;

    float acc[2][8][4];
    #pragma unroll
    for (int i = 0; i < 2; i++)
        #pragma unroll
        for (int j = 0; j < 8; j++)
            #pragma unroll
            for (int r = 0; r < 4; r++) acc[i][j][r] = 0.0f;

    // staging: A 4 float4/thread, B 4 float4/thread (rows x 8 float4-per-row)
    float4 ra[4], rb[4];
    const int arow = tid >> 3;          // +32 per j
    const int af4  = tid & 7;

    auto load_chunk = [&](int kb) {
        #pragma unroll
        for (int j = 0; j < 4; j++) {
            const int r = arow + j * 32;
            ra[j] = *(const float4*)(emb + (size_t)stok[r] * EMB + kb + af4 * 4);
            rb[j] = *(const float4*)(W_ih + (size_t)(bn * 128 + r) * EMB + kb + af4 * 4);
        }
    };
    auto store_chunk = [&]() {
        #pragma unroll
        for (int j = 0; j < 4; j++) {
            const int r = arow + j * 32;
            uint32_t* pa = sA + r * 20 + af4 * 2;
            pa[0] = pack_h2(ra[j].x, ra[j].y);
            pa[1] = pack_h2(ra[j].z, ra[j].w);
            uint32_t* pb = sB + r * 20 + af4 * 2;
            pb[0] = pack_h2(rb[j].x, rb[j].y);
            pb[1] = pack_h2(rb[j].z, rb[j].w);
        }
    };
    auto compute = [&]() {
        #pragma unroll
        for (int ks = 0; ks < 2; ks++) {
            const int k0 = ks * 8;
            uint32_t af[2][4];
            #pragma unroll
            for (int fm = 0; fm < 2; fm++) {
                const int r = wm * 32 + fm * 16 + grp;
                af[fm][0] = sA[r * 20 + k0 + q4];
                af[fm][1] = sA[(r + 8) * 20 + k0 + q4];
                af[fm][2] = sA[r * 20 + k0 + q4 + 4];
                af[fm][3] = sA[(r + 8) * 20 + k0 + q4 + 4];
            }
            #pragma unroll
            for (int fn = 0; fn < 8; fn++) {
                const int c = wn * 64 + fn * 8 + grp;
                const uint32_t b0 = sB[c * 20 + k0 + q4];
                const uint32_t b1 = sB[c * 20 + k0 + q4 + 4];
                #pragma unroll
                for (int fm = 0; fm < 2; fm++)
                    mma_f16(acc[fm][fn], af[fm], b0, b1);
            }
        }
    };

    load_chunk(0);
    store_chunk();
    __syncthreads();
    for (int kb = 0; kb < EMB; kb += 32) {
        const bool more = (kb + 32) < EMB;
        if (more) load_chunk(kb + 32);
        compute();
        __syncthreads();
        if (more) { store_chunk(); __syncthreads(); }
    }

    // epilogue: + (b_ih + b_hh), write fp32
    #pragma unroll
    for (int fm = 0; fm < 2; fm++)
        #pragma unroll
        for (int fn = 0; fn < 8; fn++) {
            const int row = bm * 128 + wm * 32 + fm * 16 + grp;
            const int col = bn * 128 + wn * 64 + fn * 8 + q4 * 2;
            const float bi0 = b_ih[col] + b_hh[col];
            const float bi1 = b_ih[col + 1] + b_hh[col + 1];
            float* o0 = g_xgates + (size_t)row * GATES + col;
            o0[0] = acc[fm][fn][0] + bi0;
            o0[1] = acc[fm][fn][1] + bi1;
            float* o1 = g_xgates + (size_t)(row + 8) * GATES + col;
            o1[0] = acc[fm][fn][2] + bi0;
            o1[1] = acc[fm][fn][3] + bi1;
        }
}

// ---------------- persistent recurrence (fp16 MMA) --------------------------
__global__ void __launch_bounds__(NTHREADS, 1)
lstm_persistent(const float* __restrict__ W_hh, float* __restrict__ out) {
    extern __shared__ char smem[];
    const uint32_t smb = smem_u32(smem);
    uint32_t* sW   = (uint32_t*)(smem + SMO_W);
    uint32_t* sAw  = (uint32_t*)(smem + SMO_A);
    float*    gbuf = (float*)(smem + SMO_GBUF);

    const int tid  = threadIdx.x;
    const int hj   = blockIdx.x * 8;
    const int lane = tid & 31;
    const int w    = tid >> 5;
    const int wm   = w & 3;          // m base wm*16
    const int wn   = w >> 2;         // n base wn*16
    const int grp  = lane >> 2;
    const int q4   = lane & 3;

    // ---- one-time: W slice (32 x 1024) -> smem fp16 ----
    for (int it = tid; it < 32 * 512; it += NTHREADS) {
        const int n  = it >> 9;
        const int w2 = it & 511;
        const float2 v = *(const float2*)(
            W_hh + (size_t)((n >> 3) * HID + hj + (n & 7)) * HID + w2 * 2);
        sW[n * SW_STRIDE + w2] = pack_h2(v.x, v.y);
    }
    __syncthreads();

    auto fill = [&](const __half* h_in, int c) {
        const int buf = c % 3;
        #pragma unroll
        for (int j = 0; j < 8; j++) {
            const int gi = tid + j * NTHREADS;
            const int b  = gi >> 5;
            const int g  = gi & 31;
            cp_async16(smb + SMO_A + (buf * SA_BUF_W + b * SA_STRIDE + g * 4) * 4,
                       h_in + (size_t)b * HID + c * 256 + g * 8);
        }
        cp_commit();
    };

    // epilogue item indices (fixed per thread)
    const int eb0 = tid >> 3,               ehh0 = tid & 7;
    const int eb1 = (tid + NTHREADS) >> 3,  ehh1 = (tid + NTHREADS) & 7;

    for (int t = 0; t < T_SEQ; t++) {
        const __half* __restrict__ h_in  = g_h[t & 1];
        __half* __restrict__       h_out = g_h[(t + 1) & 1];

        float acc[2][4] = {{0.f,0.f,0.f,0.f},{0.f,0.f,0.f,0.f}};

        fill(h_in, 0);

        // prefetch xgates for this step's epilogue (hide DRAM/L2 latency)
        float xg0[4], xg1[4];
        {
            const float* p0 = g_xgates + ((size_t)t * BATCH + eb0) * GATES + hj + ehh0;
            const float* p1 = g_xgates + ((size_t)t * BATCH + eb1) * GATES + hj + ehh1;
            #pragma unroll
            for (int g = 0; g < 4; g++) {
                xg0[g] = __ldg(p0 + g * HID);
                xg1[g] = __ldg(p1 + g * HID);
            }
        }

        #pragma unroll
        for (int c = 0; c < 4; c++) {
            if (c < 3) { fill(h_in, c + 1); cp_wait1(); }
            else       { cp_wait0(); }
            __syncthreads();

            const uint32_t* A = sAw + (c % 3) * SA_BUF_W;
            #pragma unroll
            for (int ksl = 0; ksl < 16; ksl++) {
                const int r = wm * 16 + grp;
                uint32_t af[4];
                af[0] = A[r * SA_STRIDE + ksl * 8 + q4];
                af[1] = A[(r + 8) * SA_STRIDE + ksl * 8 + q4];
                af[2] = A[r * SA_STRIDE + ksl * 8 + q4 + 4];
                af[3] = A[(r + 8) * SA_STRIDE + ksl * 8 + q4 + 4];
                const int kw = (c * 16 + ksl) * 8;
                #pragma unroll
                for (int fn = 0; fn < 2; fn++) {
                    const int n = wn * 16 + fn * 8 + grp;
                    mma_f16(acc[fn], af,
                            sW[n * SW_STRIDE + kw + q4],
                            sW[n * SW_STRIDE + kw + q4 + 4]);
                }
            }
        }

        // park recurrent-GEMM partials
        #pragma unroll
        for (int fn = 0; fn < 2; fn++) {
            const int row = wm * 16 + grp;
            const int col = wn * 16 + fn * 8 + q4 * 2;
            gbuf[row * 33 + col]           = acc[fn][0];
            gbuf[row * 33 + col + 1]       = acc[fn][1];
            gbuf[(row + 8) * 33 + col]     = acc[fn][2];
            gbuf[(row + 8) * 33 + col + 1] = acc[fn][3];
        }
        __syncthreads();

        // fused elementwise: 2 items per thread, xg already in registers
        #pragma unroll
        for (int it2 = 0; it2 < 2; it2++) {
            const int b    = it2 ? eb1 : eb0;
            const int hh   = it2 ? ehh1 : ehh0;
            const float* xg = it2 ? xg1 : xg0;
            const int hcol = hj + hh;

            const float ip = gbuf[b * 33 + hh]      + xg[0];
            const float fp = gbuf[b * 33 + 8 + hh]  + xg[1];
            const float gp = gbuf[b * 33 + 16 + hh] + xg[2];
            const float op = gbuf[b * 33 + 24 + hh] + xg[3];

            const float ig = 1.0f / (1.0f + expf(-ip));
            const float fg = 1.0f / (1.0f + expf(-fp));
            const float gg = tanhf(gp);
            const float og = 1.0f / (1.0f + expf(-op));

            const float c_old = g_c[b * HID + hcol];
            const float c_new = fg * c_old + ig * gg;
            const float h_new = og * tanhf(c_new);

            g_c[b * HID + hcol]   = c_new;
            h_out[b * HID + hcol] = __float2half_rn(h_new);
            out[((size_t)t * BATCH + b) * HID + hcol] = h_new;
        }

        // ---- grid barrier (release/acquire, wrap-safe) ----
        __syncthreads();
        if (tid == 0) {
            __threadfence();
            unsigned old;
            asm volatile("atom.add.release.gpu.global.u32 %0, [%1], 1;"
                         : "=r"(old) : "l"(&g_bar) : "memory");
            const unsigned target = old - (old % NCTA) + NCTA;
            unsigned cur;
            do {
                asm volatile("ld.acquire.gpu.global.u32 %0, [%1];"
                             : "=r"(cur) : "l"(&g_bar) : "memory");
            } while ((int)(cur - target) < 0);
        }
        __syncthreads();
    }
}

// ---------------- finalize: append (h, c) after outs ------------------------
__global__ void finalize(float* __restrict__ out) {
    int i = blockIdx.x * blockDim.x + threadIdx.x;
    if (i < BATCH * HID) {
        out[(size_t)T_SEQ * BATCH * HID + i] =
            out[(size_t)(T_SEQ - 1) * BATCH * HID + i];
        out[(size_t)T_SEQ * BATCH * HID + BATCH * HID + i] = g_c[i];
    }
}

// ---------------- launch -----------------------------------------------------
extern "C" void kernel_launch(void* const* d_in, const int* in_sizes, int n_in,
                              void* d_out, int out_size) {
    const int*   x_seq = (const int*)d_in[0];
    const float* emb   = (const float*)d_in[1];
    const float* W_ih  = (const float*)d_in[2];
    const float* W_hh  = (const float*)d_in[3];
    const float* b_ih  = (const float*)d_in[4];
    const float* b_hh  = (const float*)d_in[5];
    float* out = (float*)d_out;

    cudaFuncSetAttribute(lstm_persistent,
                         cudaFuncAttributeMaxDynamicSharedMemorySize, SMEM_BYTES);

    init_state<<<(BATCH * HID + 255) / 256, 256>>>();

    dim3 ig_grid(GATES / 128, (T_SEQ * BATCH) / 128);   // (32, 128)
    input_gemm<<<ig_grid, 256>>>(x_seq, emb, W_ih, b_ih, b_hh);

    lstm_persistent<<<NCTA, NTHREADS, SMEM_BYTES>>>(W_hh, out);

    finalize<<<(BATCH * HID + 255) / 256, 256>>>(out);
}